// round 11
// baseline (speedup 1.0000x reference)
#include <cuda_runtime.h>
#include <cuda_fp16.h>
#include <cstdint>

#define N_GENES 20000
#define UNITS   10000
#define DEG     32
#define BATCH   128

// |feature| transposed to [gene][batch] in fp16: 5.12 MB, L2-resident.
// Row = 256B; each (unit, deg) gather reads one full row, coalesced.
// The gather sits at the L2 slice-service floor (~70-75% slice efficiency
// on pseudo-random rows) — invariant across R4-R10 restructurings.
__device__ __half g_featT[(size_t)N_GENES * BATCH];

// ---------------------------------------------------------------------------
// K1: tiled transpose + fabs + fp16.  feature [128, 20000] -> featT [N, B]
// ---------------------------------------------------------------------------
__global__ void transpose_abs_kernel(const float* __restrict__ feature) {
    __shared__ float tile[32][33];               // tile[batch][gene]
    const int gx = blockIdx.x * 32;
    const int bx = blockIdx.y * 32;
    const int tx = threadIdx.x, ty = threadIdx.y;

#pragma unroll
    for (int k = 0; k < 32; k += 8)
        tile[ty + k][tx] = fabsf(feature[(size_t)(bx + ty + k) * N_GENES + (gx + tx)]);
    __syncthreads();

    const int t = ty * 32 + tx;
#pragma unroll
    for (int iter = 0; iter < 2; iter++) {
        const int tt  = iter * 256 + t;
        const int g_l = tt >> 4;                 // 0..31
        const int p   = tt & 15;                 // batch pair
        const __half2 h = __floats2half2_rn(tile[2 * p][g_l], tile[2 * p + 1][g_l]);
        *(__half2*)&g_featT[(size_t)(gx + g_l) * BATCH + bx + 2 * p] = h;
    }
}

// ---------------------------------------------------------------------------
// K2: gather-sum (best-measured R5 config). One warp per unit; each LDG.128
// covers two gene rows (half-warp per gene, 16B batch slice per lane);
// batches of 4 LDG.128 in flight. half2 accumulate, fp32 flush every 8
// genes; cross-half shfl_xor(16); smem-staged coalesced streaming output.
// ---------------------------------------------------------------------------
__global__ void __launch_bounds__(256, 5) ppi_gather_kernel(
    const int*   __restrict__ ppi,     // int32 (JAX x64-disabled)
    const float* __restrict__ kern,
    const float* __restrict__ bias,
    float*       __restrict__ out)
{
    __shared__ float tile[8][BATCH + 4];

    const int lane   = threadIdx.x & 31;
    const int hlane  = lane & 15;                 // batch-slice owner (16B)
    const int hsel   = lane >> 4;                 // 0: even gene, 1: odd gene
    const int warp   = threadIdx.x >> 5;
    const int u_base = blockIdx.x * 8;
    const int u      = u_base + warp;

    // Preamble: row byte-offset of ppi[u][lane] (row = 256B) + unit params.
    const int myoff = ppi[(size_t)u * DEG + lane] << 8;
    const float kv  = kern[u];
    const float bv  = bias[u];
    const char* base = (const char*)g_featT + hlane * 16;

    float facc[8];
#pragma unroll
    for (int j = 0; j < 8; j++) facc[j] = 0.f;

#pragma unroll
    for (int half = 0; half < 2; half++) {        // 2 flush periods x 16 genes
        __half2 hacc[4];
#pragma unroll
        for (int j = 0; j < 4; j++) hacc[j] = __floats2half2_rn(0.f, 0.f);

#pragma unroll
        for (int bb = 0; bb < 2; bb++) {          // 2 batches of 4 LDG.128
            uint4 raw[4];
#pragma unroll
            for (int q = 0; q < 4; q++) {
                const int it  = half * 8 + bb * 4 + q;          // 0..15
                const int off = __shfl_sync(0xffffffffu, myoff, 2 * it + hsel);
                raw[q] = *(const uint4*)(base + off);
            }
#pragma unroll
            for (int q = 0; q < 4; q++) {
                hacc[0] = __hadd2(hacc[0], *(const __half2*)&raw[q].x);
                hacc[1] = __hadd2(hacc[1], *(const __half2*)&raw[q].y);
                hacc[2] = __hadd2(hacc[2], *(const __half2*)&raw[q].z);
                hacc[3] = __hadd2(hacc[3], *(const __half2*)&raw[q].w);
            }
        }
#pragma unroll
        for (int j = 0; j < 4; j++) {             // fp32 flush
            const float2 f = __half22float2(hacc[j]);
            facc[2 * j]     += f.x;
            facc[2 * j + 1] += f.y;
        }
    }

    // Combine the two half-warps (same batch slice, disjoint gene subsets).
#pragma unroll
    for (int j = 0; j < 8; j++)
        facc[j] += __shfl_xor_sync(0xffffffffu, facc[j], 16);

    if (lane < 16) {                              // conflict-free 512B row
        float r[8];
#pragma unroll
        for (int j = 0; j < 8; j++)
            r[j] = tanhf(fmaf(facc[j], kv, bv));
        *(float4*)&tile[warp][hlane * 8]     = make_float4(r[0], r[1], r[2], r[3]);
        *(float4*)&tile[warp][hlane * 8 + 4] = make_float4(r[4], r[5], r[6], r[7]);
    }
    __syncthreads();

    // Coalesced streaming output (write-once; keep out of the hot L2 set):
    // 8-thread groups write contiguous 32B chunks per batch row.
    for (int t = threadIdx.x; t < BATCH * 8; t += 256) {
        const int u_l = t & 7;
        const int b   = t >> 3;
        __stcs(&out[(size_t)b * UNITS + (u_base + u_l)], tile[u_l][b]);
    }
}

// ---------------------------------------------------------------------------
extern "C" void kernel_launch(void* const* d_in, const int* in_sizes, int n_in,
                              void* d_out, int out_size) {
    const float* feature = (const float*)d_in[0];
    const int*   ppi     = (const int*)d_in[1];
    const float* kern    = (const float*)d_in[2];
    const float* bias    = (const float*)d_in[3];
    float*       out     = (float*)d_out;

    dim3 tgrid(N_GENES / 32, BATCH / 32);   // (625, 4)
    dim3 tblock(32, 8);
    transpose_abs_kernel<<<tgrid, tblock>>>(feature);

    ppi_gather_kernel<<<UNITS / 8, 256>>>(ppi, kern, bias, out);  // 1250 CTAs
}

// round 12
// speedup vs baseline: 1.4307x; 1.4307x over previous
#include <cuda_runtime.h>
#include <cuda_fp16.h>
#include <cstdint>

#define N_GENES 20000
#define UNITS   10000
#define DEG     32
#define BATCH   128

// |feature| transposed to [gene][batch] in fp16: 5.12 MB, L2-resident.
// Row = 256B; each (unit, deg) gather reads one full row, coalesced.
// The gather sits at the L2 slice-service cap (~28% of theoretical LTS
// peak == the HW-achievable ceiling) — invariant across R4-R11.
__device__ __half g_featT[(size_t)N_GENES * BATCH];

// ---------------------------------------------------------------------------
// K1: transpose + fabs + fp16.  feature [128, 20000] -> featT [N, B].
// One CTA per 32-gene column block covering the FULL batch: each gene's
// 256B featT row is written contiguously by one 64-thread group.
// ---------------------------------------------------------------------------
__global__ void __launch_bounds__(256) transpose_abs_kernel(
    const float* __restrict__ feature)
{
    __shared__ float tile[BATCH][33];            // tile[batch][gene], 16.9 KB
    const int gx  = blockIdx.x * 32;
    const int tx  = threadIdx.x & 31;            // gene within block
    const int row = threadIdx.x >> 5;            // batch row 0..7

    // Load: 16 iterations of fully-coalesced 128B row segments per warp.
#pragma unroll
    for (int k = 0; k < BATCH; k += 8)
        tile[row + k][tx] = fabsf(feature[(size_t)(row + k) * N_GENES + (gx + tx)]);
    __syncthreads();

    // Store: 32 genes x 64 half2 = 2048 tasks; 64 consecutive threads emit
    // one contiguous 256B gene row.
#pragma unroll
    for (int tt = 0; tt < 8; tt++) {
        const int task = tt * 256 + threadIdx.x;
        const int g_l  = task >> 6;              // 0..31
        const int p    = task & 63;              // batch pair
        const __half2 h = __floats2half2_rn(tile[2 * p][g_l], tile[2 * p + 1][g_l]);
        *(__half2*)&g_featT[(size_t)(gx + g_l) * BATCH + 2 * p] = h;
    }
}

// ---------------------------------------------------------------------------
// K2: gather-sum (best-measured config, 10.78-10.94us node). One warp per
// unit; each LDG.128 covers two gene rows (half-warp per gene, 16B batch
// slice per lane); batches of 4 LDG.128 in flight. half2 accumulate, fp32
// flush every 8 genes; cross-half shfl_xor(16); streaming smem-staged output.
// ---------------------------------------------------------------------------
__global__ void __launch_bounds__(256, 5) ppi_gather_kernel(
    const int*   __restrict__ ppi,     // int32 (JAX x64-disabled)
    const float* __restrict__ kern,
    const float* __restrict__ bias,
    float*       __restrict__ out)
{
    __shared__ float tile[8][BATCH + 4];

    const int lane   = threadIdx.x & 31;
    const int hlane  = lane & 15;                 // batch-slice owner (16B)
    const int hsel   = lane >> 4;                 // 0: even gene, 1: odd gene
    const int warp   = threadIdx.x >> 5;
    const int u_base = blockIdx.x * 8;
    const int u      = u_base + warp;

    // Preamble: row byte-offset of ppi[u][lane] (row = 256B) + unit params.
    const int myoff = ppi[(size_t)u * DEG + lane] << 8;
    const float kv  = kern[u];
    const float bv  = bias[u];
    const char* base = (const char*)g_featT + hlane * 16;

    float facc[8];
#pragma unroll
    for (int j = 0; j < 8; j++) facc[j] = 0.f;

#pragma unroll
    for (int half = 0; half < 2; half++) {        // 2 flush periods x 16 genes
        __half2 hacc[4];
#pragma unroll
        for (int j = 0; j < 4; j++) hacc[j] = __floats2half2_rn(0.f, 0.f);

#pragma unroll
        for (int bb = 0; bb < 2; bb++) {          // 2 batches of 4 LDG.128
            uint4 raw[4];
#pragma unroll
            for (int q = 0; q < 4; q++) {
                const int it  = half * 8 + bb * 4 + q;          // 0..15
                const int off = __shfl_sync(0xffffffffu, myoff, 2 * it + hsel);
                raw[q] = *(const uint4*)(base + off);
            }
#pragma unroll
            for (int q = 0; q < 4; q++) {
                hacc[0] = __hadd2(hacc[0], *(const __half2*)&raw[q].x);
                hacc[1] = __hadd2(hacc[1], *(const __half2*)&raw[q].y);
                hacc[2] = __hadd2(hacc[2], *(const __half2*)&raw[q].z);
                hacc[3] = __hadd2(hacc[3], *(const __half2*)&raw[q].w);
            }
        }
#pragma unroll
        for (int j = 0; j < 4; j++) {             // fp32 flush
            const float2 f = __half22float2(hacc[j]);
            facc[2 * j]     += f.x;
            facc[2 * j + 1] += f.y;
        }
    }

    // Combine the two half-warps (same batch slice, disjoint gene subsets).
#pragma unroll
    for (int j = 0; j < 8; j++)
        facc[j] += __shfl_xor_sync(0xffffffffu, facc[j], 16);

    if (lane < 16) {                              // conflict-free 512B row
        float r[8];
#pragma unroll
        for (int j = 0; j < 8; j++)
            r[j] = tanhf(fmaf(facc[j], kv, bv));
        *(float4*)&tile[warp][hlane * 8]     = make_float4(r[0], r[1], r[2], r[3]);
        *(float4*)&tile[warp][hlane * 8 + 4] = make_float4(r[4], r[5], r[6], r[7]);
    }
    __syncthreads();

    // Coalesced streaming output (write-once; keep out of the hot L2 set):
    // 8-thread groups write contiguous 32B chunks per batch row.
    for (int t = threadIdx.x; t < BATCH * 8; t += 256) {
        const int u_l = t & 7;
        const int b   = t >> 3;
        __stcs(&out[(size_t)b * UNITS + (u_base + u_l)], tile[u_l][b]);
    }
}

// ---------------------------------------------------------------------------
extern "C" void kernel_launch(void* const* d_in, const int* in_sizes, int n_in,
                              void* d_out, int out_size) {
    const float* feature = (const float*)d_in[0];
    const int*   ppi     = (const int*)d_in[1];
    const float* kern    = (const float*)d_in[2];
    const float* bias    = (const float*)d_in[3];
    float*       out     = (float*)d_out;

    transpose_abs_kernel<<<N_GENES / 32, 256>>>(feature);       // 625 CTAs
    ppi_gather_kernel<<<UNITS / 8, 256>>>(ppi, kern, bias, out); // 1250 CTAs
}